// round 1
// baseline (speedup 1.0000x reference)
#include <cuda_runtime.h>
#include <cuda_bf16.h>

// Shapes (fixed by the problem): T=1024, B=8, D=64, N=64
#define T_DIM 1024
#define B_DIM 8
#define D_DIM 64
#define N_DIM 64
#define BN    (B_DIM * N_DIM)      // 512
#define CH    32                   // number of T-chunks
#define TC    (T_DIM / CH)         // 32 timesteps per chunk
#define EPSV  1e-8f

// Scratch (device globals: allocation-free)
__device__ float  gW[T_DIM * BN];                       // w[t,b,n] = k * decay   (2 MB)
__device__ float4 gC[CH * B_DIM * D_DIM * N_DIM / 4];   // chunk sums             (4 MB)
__device__ float4 gP[CH * B_DIM * D_DIM * N_DIM / 4];   // exclusive chunk prefix (4 MB)

// ---------------------------------------------------------------------------
// K1: per (b,n) sequence: logc = cumsum(log(max(alpha,eps))) over T (block scan),
//     decay = exp(logc) / (exp(logc_last)+eps),  w = k * decay
// grid = 512 blocks (one per (b,n)), 256 threads, 4 timesteps per thread.
// ---------------------------------------------------------------------------
__global__ void k_decay(const float* __restrict__ kk,
                        const float* __restrict__ alpha) {
    const int bn  = blockIdx.x;          // b*64 + n
    const int tid = threadIdx.x;         // 0..255
    const int t0  = tid * 4;

    float c[4];
    float run = 0.f;
#pragma unroll
    for (int i = 0; i < 4; i++) {
        float a = alpha[(t0 + i) * BN + bn];
        run += logf(fmaxf(a, EPSV));
        c[i] = run;                       // local inclusive cumsum
    }

    // inclusive warp scan of per-thread totals
    float v = run;
#pragma unroll
    for (int o = 1; o < 32; o <<= 1) {
        float x = __shfl_up_sync(0xFFFFFFFFu, v, o);
        if ((tid & 31) >= o) v += x;
    }

    __shared__ float wsum[8];
    if ((tid & 31) == 31) wsum[tid >> 5] = v;
    __syncthreads();
    if (tid < 8) {
        float s = wsum[tid];
#pragma unroll
        for (int o = 1; o < 8; o <<= 1) {
            float x = __shfl_up_sync(0xFFu, s, o);
            if (tid >= o) s += x;
        }
        wsum[tid] = s;                    // inclusive scan of warp sums
    }
    __syncthreads();

    const int warp = tid >> 5;
    float warpoff = (warp > 0) ? wsum[warp - 1] : 0.f;
    float exwarp  = __shfl_up_sync(0xFFFFFFFFu, v, 1);
    if ((tid & 31) == 0) exwarp = 0.f;
    const float excl  = warpoff + exwarp;     // exclusive prefix for this thread
    const float total = wsum[7];              // logc at t = T-1
    const float inv   = 1.f / (expf(total) + EPSV);

#pragma unroll
    for (int i = 0; i < 4; i++) {
        float logc  = excl + c[i];
        float decay = expf(logc) * inv;
        gW[(t0 + i) * BN + bn] = kk[(t0 + i) * BN + bn] * decay;
    }
}

// ---------------------------------------------------------------------------
// K2: chunk sums  C[c,b,d,n] = sum_{t in chunk c} v[t,b,d] * w[t,b,n]
// grid = (CH, B), 256 threads; each thread owns a 4x4 (d,n) sub-tile.
// ---------------------------------------------------------------------------
__global__ void k_chunksum(const float* __restrict__ vv) {
    const int c = blockIdx.x, b = blockIdx.y;
    const int tid = threadIdx.x;             // 0..255

    __shared__ float sv[TC][D_DIM];
    __shared__ float sw[TC][N_DIM];

    for (int i = tid; i < TC * 64; i += 256) {
        int t = i >> 6, j = i & 63;
        int g = ((c * TC + t) * B_DIM + b) * 64 + j;
        sv[t][j] = vv[g];
        sw[t][j] = gW[(c * TC + t) * BN + b * N_DIM + j];
    }
    __syncthreads();

    const int dq = tid >> 4;                 // 0..15 -> d rows dq*4..+3
    const int nq = tid & 15;                 // 0..15 -> n cols nq*4..+3

    float acc[4][4] = {};
#pragma unroll
    for (int t = 0; t < TC; t++) {
        float4 av = *(const float4*)&sv[t][dq * 4];
        float4 aw = *(const float4*)&sw[t][nq * 4];
        float va[4] = {av.x, av.y, av.z, av.w};
        float wa[4] = {aw.x, aw.y, aw.z, aw.w};
#pragma unroll
        for (int i = 0; i < 4; i++)
#pragma unroll
            for (int j = 0; j < 4; j++)
                acc[i][j] += va[i] * wa[j];
    }

#pragma unroll
    for (int i = 0; i < 4; i++) {
        float4 st = make_float4(acc[i][0], acc[i][1], acc[i][2], acc[i][3]);
        // float4 index of (d = dq*4+i, n4 = nq) within [c][b] tile: d*16 + nq
        gC[(c * B_DIM + b) * 1024 + (dq * 4 + i) * 16 + nq] = st;
    }
}

// ---------------------------------------------------------------------------
// K3: exclusive prefix over chunks: P[c] = sum_{c'<c} C[c']
// grid = B*16 blocks, 64 threads; thread owns one float4 lane across all chunks.
// ---------------------------------------------------------------------------
__global__ void k_prefix() {
    const int b = blockIdx.x & 7;
    const int s = blockIdx.x >> 3;           // 0..15
    const int e = s * 64 + threadIdx.x;      // float4 index 0..1023 within (b) tile

    float4 run = make_float4(0.f, 0.f, 0.f, 0.f);
#pragma unroll
    for (int c = 0; c < CH; c++) {
        int idx = (c * B_DIM + b) * 1024 + e;
        float4 x = gC[idx];
        gP[idx] = run;
        run.x += x.x; run.y += x.y; run.z += x.z; run.w += x.w;
    }
}

// ---------------------------------------------------------------------------
// K4: main writer.  acc = P[c,b];  for t in chunk: acc += v[t,d]*w[t,n]; store S[t].
// grid = (CH, B), 1024 threads; thread = (d = tid/16, n4 = tid%16), float4 in n.
// Each t writes one fully-contiguous 16KB row -> perfect store coalescing.
// ---------------------------------------------------------------------------
__global__ void __launch_bounds__(1024, 2)
k_main(const float* __restrict__ vv, float4* __restrict__ out) {
    const int c = blockIdx.x, b = blockIdx.y;
    const int tid = threadIdx.x;             // 0..1023

    __shared__ float  sv[TC][D_DIM];
    __shared__ float4 sw4[TC][16];

    for (int i = tid; i < TC * 64; i += 1024) {
        int t = i >> 6, j = i & 63;
        sv[t][j] = vv[((c * TC + t) * B_DIM + b) * 64 + j];
        ((float*)sw4)[t * 64 + j] = gW[(c * TC + t) * BN + b * N_DIM + j];
    }
    __syncthreads();

    const int d  = tid >> 4;
    const int nq = tid & 15;

    float4 acc = gP[(c * B_DIM + b) * 1024 + tid];   // tid == d*16+nq matches layout

#pragma unroll
    for (int t = 0; t < TC; t++) {
        float  vt = sv[t][d];
        float4 wt = sw4[t][nq];
        acc.x += vt * wt.x;
        acc.y += vt * wt.y;
        acc.z += vt * wt.z;
        acc.w += vt * wt.w;
        out[((c * TC + t) * B_DIM + b) * 1024 + tid] = acc;
    }
}

// ---------------------------------------------------------------------------
extern "C" void kernel_launch(void* const* d_in, const int* in_sizes, int n_in,
                              void* d_out, int out_size) {
    (void)in_sizes; (void)n_in; (void)out_size;
    const float* v     = (const float*)d_in[0];
    const float* k     = (const float*)d_in[1];
    const float* alpha = (const float*)d_in[2];
    float4* out = (float4*)d_out;

    k_decay<<<BN, 256>>>(k, alpha);
    k_chunksum<<<dim3(CH, B_DIM), 256>>>(v);
    k_prefix<<<B_DIM * 16, 64>>>();
    k_main<<<dim3(CH, B_DIM), 1024>>>(v, out);
}